// round 16
// baseline (speedup 1.0000x reference)
#include <cuda_runtime.h>
#include <cuda_bf16.h>
#include <cuda_fp16.h>
#include <cstdint>

#define NN 50000
#define NE 800000
#define DD 128
#define NL 4
#define EPS 1e-5f
#define TILES 391
#define TSTRB 144
#define CHB   (128 * TSTRB)
#define TILEB (2 * CHB)
#define TILE_ULL (TILEB / 8)

// ---------------- device scratch ----------------
__device__ __half g_hw[NN * DD];
__device__ float g_hr[NN * DD];
__device__ float g_agg[NN * DD];
__device__ int   g_counts[NN];
__device__ int   g_offsets[NN];
__device__ int   g_cursor[NN];
__device__ int   g_csr_src[NE];
__device__ float g_csr_norm[NE];
__device__ float g_dinv[NN];
__device__ float g_colsum[NL * DD];
__device__ float g_colsq[NL * DD];
__device__ int   g_total;
__device__ int   g_is64;
__device__ unsigned long long g_ah[TILES * TILE_ULL];
__device__ unsigned long long g_al[TILES * TILE_ULL];
__device__ unsigned long long g_wt[NL * 2 * 2 * TILE_ULL];

// ---------------- stream/event pool (created at static init, pre-baseline) ----------
struct SideStream {
    cudaStream_t s = nullptr;
    cudaEvent_t  evA[NL] = {};
    cudaEvent_t  evB[NL] = {};
    SideStream() {
        cudaFree(0);  // force context init now
        cudaStreamCreateWithFlags(&s, cudaStreamNonBlocking);
        for (int i = 0; i < NL; i++) {
            cudaEventCreateWithFlags(&evA[i], cudaEventDisableTiming);
            cudaEventCreateWithFlags(&evB[i], cudaEventDisableTiming);
        }
    }
};
static SideStream g_ss;

// ---------------- helpers ----------------
__device__ __forceinline__ uint32_t smem_u32(const void* p) {
    uint32_t a;
    asm("{ .reg .u64 t; cvta.to.shared.u64 t, %1; cvt.u32.u64 %0, t; }" : "=r"(a) : "l"(p));
    return a;
}
__device__ __forceinline__ void cp16(uint32_t dst, const void* src) {
    asm volatile("cp.async.cg.shared.global [%0], [%1], 16;" :: "r"(dst), "l"(src));
}
__device__ __forceinline__ void cp_commit_wait() {
    asm volatile("cp.async.commit_group;");
    asm volatile("cp.async.wait_group 0;" ::: "memory");
}
__device__ __forceinline__ void ldm_x4(uint32_t a, uint32_t* r) {
    asm volatile("ldmatrix.sync.aligned.m8n8.x4.shared.b16 {%0,%1,%2,%3}, [%4];"
                 : "=r"(r[0]), "=r"(r[1]), "=r"(r[2]), "=r"(r[3]) : "r"(a));
}
__device__ __forceinline__ void mma16816(float* d, const uint32_t* a, const uint32_t* b) {
    asm volatile(
        "mma.sync.aligned.m16n8k16.row.col.f32.bf16.bf16.f32 "
        "{%0,%1,%2,%3}, {%4,%5,%6,%7}, {%8,%9}, {%0,%1,%2,%3};"
        : "+f"(d[0]), "+f"(d[1]), "+f"(d[2]), "+f"(d[3])
        : "r"(a[0]), "r"(a[1]), "r"(a[2]), "r"(a[3]), "r"(b[0]), "r"(b[1]));
}
__device__ __forceinline__ void split4(const float* v, unsigned long long& hp, unsigned long long& lp) {
    unsigned int hu[2], lu[2];
#pragma unroll
    for (int j = 0; j < 2; j++) {
        __nv_bfloat16 h0 = __float2bfloat16(v[2 * j + 0]);
        __nv_bfloat16 h1 = __float2bfloat16(v[2 * j + 1]);
        __nv_bfloat16 l0 = __float2bfloat16(v[2 * j + 0] - __bfloat162float(h0));
        __nv_bfloat16 l1 = __float2bfloat16(v[2 * j + 1] - __bfloat162float(h1));
        unsigned short a = *(unsigned short*)&h0, b = *(unsigned short*)&h1;
        unsigned short c = *(unsigned short*)&l0, d = *(unsigned short*)&l1;
        hu[j] = (unsigned)a | ((unsigned)b << 16);
        lu[j] = (unsigned)c | ((unsigned)d << 16);
    }
    hp = (unsigned long long)hu[0] | ((unsigned long long)hu[1] << 32);
    lp = (unsigned long long)lu[0] | ((unsigned long long)lu[1] << 32);
}
__device__ __forceinline__ uint32_t tile_off(int r, int k) {
    return (uint32_t)((k >> 6) * CHB + r * TSTRB + (k & 63) * 2);
}
__device__ __forceinline__ float4 h4f(uint2 u) {
    __half2 p0 = *(__half2*)&u.x;
    __half2 p1 = *(__half2*)&u.y;
    float2 f0 = __half22float2(p0);
    float2 f1 = __half22float2(p1);
    return make_float4(f0.x, f0.y, f1.x, f1.y);
}

// ---------------- detect dtype + zero counts/stats ----------------
__global__ void detect_kernel(const int* __restrict__ ei32) {
    __shared__ int s_or;
    if (threadIdx.x == 0) { s_or = 0; g_total = 0; }
    __syncthreads();
    int acc = 0;
    for (int i = threadIdx.x; i < 2048; i += blockDim.x)
        acc |= ei32[2 * i + 1];
    atomicOr(&s_or, acc);
    for (int i = threadIdx.x; i < NL * DD; i += blockDim.x) {
        g_colsum[i] = 0.f;
        g_colsq[i]  = 0.f;
    }
    for (int i = threadIdx.x; i < NN; i += blockDim.x) g_counts[i] = 0;
    __syncthreads();
    if (threadIdx.x == 0) g_is64 = (s_or == 0) ? 1 : 0;
}
__device__ __forceinline__ int edge_at(const void* ei, long long idx) {
    if (g_is64) return (int)((const long long*)ei)[idx];
    return ((const int*)ei)[idx];
}
__global__ void hist_kernel(const void* __restrict__ ei) {
    int e = blockIdx.x * blockDim.x + threadIdx.x;
    if (e < NE) {
        int dst = edge_at(ei, (long long)NE + e);
        if ((unsigned)dst < NN) atomicAdd(&g_counts[dst], 1);
    }
}
__global__ void offsets_kernel() {
    int i    = blockIdx.x * blockDim.x + threadIdx.x;
    int lane = threadIdx.x & 31;
    int v = (i < NN) ? g_counts[i] : 0;
    int s = v;
#pragma unroll
    for (int off = 1; off < 32; off <<= 1) {
        int t = __shfl_up_sync(0xffffffffu, s, off);
        if (lane >= off) s += t;
    }
    int wtot = __shfl_sync(0xffffffffu, s, 31);
    int base = 0;
    if (lane == 0) base = atomicAdd(&g_total, wtot);
    base = __shfl_sync(0xffffffffu, base, 0);
    if (i < NN) {
        g_offsets[i] = base + s - v;
        g_cursor[i]  = base + s - v;
        g_dinv[i]    = rsqrtf((float)(v + 2));
    }
}
__global__ void fill_kernel(const void* __restrict__ ei) {
    int e = blockIdx.x * blockDim.x + threadIdx.x;
    if (e < NE) {
        int src = edge_at(ei, e);
        int dst = edge_at(ei, (long long)NE + e);
        if ((unsigned)src < NN && (unsigned)dst < NN) {
            int p = atomicAdd(&g_cursor[dst], 1);
            g_csr_src[p] = src;
            g_csr_norm[p] = g_dinv[src] * g_dinv[dst];
        }
    }
}

// ---------------- weight prep ----------------
__global__ void prep_w_kernel(const float* __restrict__ conv_w, const float* __restrict__ res_w) {
    int l = blockIdx.x >> 1, mat = blockIdx.x & 1;
    const float* W = (mat ? res_w : conv_w) + (size_t)l * DD * DD;
    char* hi = (char*)(g_wt + ((size_t)(l * 2 + mat) * 2 + 0) * TILE_ULL);
    char* lo = (char*)(g_wt + ((size_t)(l * 2 + mat) * 2 + 1) * TILE_ULL);
    for (int idx = threadIdx.x; idx < 128 * 32; idx += blockDim.x) {
        int r = idx & 127;
        int c = (idx >> 7) * 4;
        float v[4];
#pragma unroll
        for (int j = 0; j < 4; j++) v[j] = W[(size_t)(c + j) * DD + r];
        unsigned long long hp, lp;
        split4(v, hp, lp);
        uint32_t a = tile_off(r, c);
        *(unsigned long long*)(hi + a) = hp;
        *(unsigned long long*)(lo + a) = lp;
    }
}

// ---------------- x prep ----------------
__global__ void prep_x_kernel(const float* __restrict__ x) {
    int idx = blockIdx.x * blockDim.x + threadIdx.x;
    if (idx >= TILES * 128 * 32) return;
    int tile = idx >> 12;
    int rem  = idx & 4095;
    int r = rem >> 5;
    int c = (rem & 31) * 4;
    int row = tile * 128 + r;
    float v[4] = {0.f, 0.f, 0.f, 0.f};
    if (row < NN) {
        float4 t = *((const float4*)(x + (size_t)row * DD + c));
        v[0] = t.x; v[1] = t.y; v[2] = t.z; v[3] = t.w;
    }
    unsigned long long hp, lp;
    split4(v, hp, lp);
    uint32_t a = tile_off(r, c);
    *(unsigned long long*)((char*)g_ah + (size_t)tile * TILEB + a) = hp;
    *(unsigned long long*)((char*)g_al + (size_t)tile * TILEB + a) = lp;
}

// ---------------- single-matrix tensor-core GEMM core ----------
// smem: Ah | Al | Wh | Wl = 4 x 36864 = 147456 B. 512 thr, warp grid 4x4.
#define SM_AH 0
#define SM_AL TILEB
#define SM_WH (2 * TILEB)
#define SM_WL (3 * TILEB)
#define SM_TOT4 (4 * TILEB)

// computes acc[2][4][4] = A_tile @ W (bf16 hi/lo 3-term)
__device__ __forceinline__ void gemm_core(
    uint32_t sb, int tile, const char* gW, float acc[2][4][4],
    int tid, int lane, int wm, int wn)
{
    const char* gAh = (const char*)g_ah + (size_t)tile * TILEB;
    const char* gAl = (const char*)g_al + (size_t)tile * TILEB;

    for (int i = tid; i < TILEB / 16; i += 512) {
        uint32_t o = (uint32_t)i * 16;
        cp16(sb + SM_AH + o, gAh + o);
        cp16(sb + SM_AL + o, gAl + o);
        cp16(sb + SM_WH + o, gW + o);
        cp16(sb + SM_WL + o, gW + TILEB + o);
    }

    int la  = (lane & 7) + ((lane & 8) ? 8 : 0);
    uint32_t aka = (lane & 16) ? 16 : 0;
    int lb  = (lane & 7) + ((lane & 16) ? 8 : 0);
    uint32_t akb = (lane & 8) ? 16 : 0;

    uint32_t aA = sb + SM_AH + (uint32_t)(wm * 32 + la) * TSTRB + aka;
    uint32_t aB = sb + SM_WH + (uint32_t)(wn * 32 + lb) * TSTRB + akb;

    cp_commit_wait();
    __syncthreads();

#pragma unroll
    for (int ks = 0; ks < 8; ks++) {
        uint32_t kb = (uint32_t)((ks >> 2) * CHB + (ks & 3) * 32);
        uint32_t ah0[4], ah1[4], al0[4], al1[4];
        ldm_x4(aA + kb, ah0);
        ldm_x4(aA + 16 * TSTRB + kb, ah1);
        ldm_x4(aA + TILEB + kb, al0);
        ldm_x4(aA + TILEB + 16 * TSTRB + kb, al1);
        uint32_t bh[4][2];
#pragma unroll
        for (int g2 = 0; g2 < 2; g2++) {
            uint32_t t[4];
            ldm_x4(aB + (uint32_t)g2 * 16 * TSTRB + kb, t);
            bh[2 * g2][0] = t[0]; bh[2 * g2][1] = t[1];
            bh[2 * g2 + 1][0] = t[2]; bh[2 * g2 + 1][1] = t[3];
        }
#pragma unroll
        for (int n = 0; n < 4; n++) {
            mma16816(acc[0][n], ah0, bh[n]);
            mma16816(acc[1][n], ah1, bh[n]);
            mma16816(acc[0][n], al0, bh[n]);
            mma16816(acc[1][n], al1, bh[n]);
        }
        uint32_t bl[4][2];
#pragma unroll
        for (int g2 = 0; g2 < 2; g2++) {
            uint32_t t[4];
            ldm_x4(aB + TILEB + (uint32_t)g2 * 16 * TSTRB + kb, t);
            bl[2 * g2][0] = t[0]; bl[2 * g2][1] = t[1];
            bl[2 * g2 + 1][0] = t[2]; bl[2 * g2 + 1][1] = t[3];
        }
#pragma unroll
        for (int n = 0; n < 4; n++) {
            mma16816(acc[0][n], ah0, bl[n]);
            mma16816(acc[1][n], ah1, bl[n]);
        }
    }
    __syncthreads();
}

__global__ void __launch_bounds__(512, 1) gemm_conv_kernel(int layer, __half* __restrict__ C)
{
    extern __shared__ char smem[];
    uint32_t sb = smem_u32(smem);
    int tid = threadIdx.x, lane = tid & 31, w = tid >> 5;
    int wm = w >> 2, wn = w & 3;
    int tile = blockIdx.x;
    const char* gW = (const char*)(g_wt + ((size_t)(layer * 2 + 0) * 2) * TILE_ULL);

    float acc[2][4][4];
#pragma unroll
    for (int a = 0; a < 2; a++)
#pragma unroll
        for (int c = 0; c < 4; c++)
#pragma unroll
            for (int d = 0; d < 4; d++) acc[a][c][d] = 0.f;

    gemm_core(sb, tile, gW, acc, tid, lane, wm, wn);

    int grp = lane >> 2, tig = lane & 3;
#pragma unroll
    for (int ni = 0; ni < 4; ni++) {
        int col = wn * 32 + ni * 8 + tig * 2;
#pragma unroll
        for (int mi = 0; mi < 2; mi++) {
            int row0 = tile * 128 + wm * 32 + mi * 16 + grp;
            if (row0 < NN) {
                __half2 o = __floats2half2_rn(acc[mi][ni][0], acc[mi][ni][1]);
                *(__half2*)(C + (size_t)row0 * DD + col) = o;
            }
            if (row0 + 8 < NN) {
                __half2 o = __floats2half2_rn(acc[mi][ni][2], acc[mi][ni][3]);
                *(__half2*)(C + (size_t)(row0 + 8) * DD + col) = o;
            }
        }
    }
}

__global__ void __launch_bounds__(512, 1) gemm_res_kernel(
    const float* __restrict__ res_b, int layer, float* __restrict__ C)
{
    extern __shared__ char smem[];
    uint32_t sb = smem_u32(smem);
    int tid = threadIdx.x, lane = tid & 31, w = tid >> 5;
    int wm = w >> 2, wn = w & 3;
    int tile = blockIdx.x;
    const char* gW = (const char*)(g_wt + ((size_t)(layer * 2 + 1) * 2) * TILE_ULL);

    float acc[2][4][4];
#pragma unroll
    for (int a = 0; a < 2; a++)
#pragma unroll
        for (int c = 0; c < 4; c++)
#pragma unroll
            for (int d = 0; d < 4; d++) acc[a][c][d] = 0.f;

    gemm_core(sb, tile, gW, acc, tid, lane, wm, wn);

    int grp = lane >> 2, tig = lane & 3;
#pragma unroll
    for (int ni = 0; ni < 4; ni++) {
        int col = wn * 32 + ni * 8 + tig * 2;
        float2 bv = *(const float2*)&res_b[col];
#pragma unroll
        for (int mi = 0; mi < 2; mi++) {
            int row0 = tile * 128 + wm * 32 + mi * 16 + grp;
            if (row0 < NN) {
                float2 o = make_float2(acc[mi][ni][0] + bv.x, acc[mi][ni][1] + bv.y);
                *(float2*)(C + (size_t)row0 * DD + col) = o;
            }
            if (row0 + 8 < NN) {
                float2 o = make_float2(acc[mi][ni][2] + bv.x, acc[mi][ni][3] + bv.y);
                *(float2*)(C + (size_t)(row0 + 8) * DD + col) = o;
            }
        }
    }
}

// ---------------- aggregation + BN stats: 4 nodes/warp, fp16 gathers ----
__global__ void __launch_bounds__(256) agg_kernel(const float* __restrict__ conv_b,
                                                  float* __restrict__ colsum,
                                                  float* __restrict__ colsq)
{
    __shared__ float s_sum[DD];
    __shared__ float s_sq[DD];
    int tid = threadIdx.x;
    if (tid < DD) { s_sum[tid] = 0.f; s_sq[tid] = 0.f; }
    __syncthreads();

    int warp = tid >> 5, lane = tid & 31;
    int node0 = blockIdx.x * 32 + warp * 4;
    const uint2* __restrict__ hwv = (const uint2*)g_hw;
    const int*   __restrict__ csrc = g_csr_src;
    const float* __restrict__ cnrm = g_csr_norm;
    float4 b = ((const float4*)conv_b)[lane];

    float lsum[4] = {0.f, 0.f, 0.f, 0.f};
    float lsq[4]  = {0.f, 0.f, 0.f, 0.f};

#pragma unroll
    for (int nn = 0; nn < 4; nn++) {
        int node = node0 + nn;
        if (node >= NN) break;

        float di = g_dinv[node];
        float ws = 2.f * di * di;
        float4 hs = h4f(hwv[(size_t)node * 32 + lane]);
        float4 a0, a1, a2, a3;
        a0.x = ws * hs.x; a0.y = ws * hs.y; a0.z = ws * hs.z; a0.w = ws * hs.w;
        a1 = make_float4(0.f, 0.f, 0.f, 0.f);
        a2 = make_float4(0.f, 0.f, 0.f, 0.f);
        a3 = make_float4(0.f, 0.f, 0.f, 0.f);

        int s = g_offsets[node];
        int e = s + g_counts[node];
        int i = s;
        for (; i + 4 <= e; i += 4) {
            int   s0 = __ldg(&csrc[i + 0]), s1 = __ldg(&csrc[i + 1]);
            int   s2 = __ldg(&csrc[i + 2]), s3 = __ldg(&csrc[i + 3]);
            float w0 = __ldg(&cnrm[i + 0]), w1 = __ldg(&cnrm[i + 1]);
            float w2 = __ldg(&cnrm[i + 2]), w3 = __ldg(&cnrm[i + 3]);
            float4 h0 = h4f(hwv[(size_t)s0 * 32 + lane]);
            float4 h1 = h4f(hwv[(size_t)s1 * 32 + lane]);
            float4 h2 = h4f(hwv[(size_t)s2 * 32 + lane]);
            float4 h3 = h4f(hwv[(size_t)s3 * 32 + lane]);
            a0.x = fmaf(w0, h0.x, a0.x); a0.y = fmaf(w0, h0.y, a0.y);
            a0.z = fmaf(w0, h0.z, a0.z); a0.w = fmaf(w0, h0.w, a0.w);
            a1.x = fmaf(w1, h1.x, a1.x); a1.y = fmaf(w1, h1.y, a1.y);
            a1.z = fmaf(w1, h1.z, a1.z); a1.w = fmaf(w1, h1.w, a1.w);
            a2.x = fmaf(w2, h2.x, a2.x); a2.y = fmaf(w2, h2.y, a2.y);
            a2.z = fmaf(w2, h2.z, a2.z); a2.w = fmaf(w2, h2.w, a2.w);
            a3.x = fmaf(w3, h3.x, a3.x); a3.y = fmaf(w3, h3.y, a3.y);
            a3.z = fmaf(w3, h3.z, a3.z); a3.w = fmaf(w3, h3.w, a3.w);
        }
        for (; i < e; i++) {
            int   ss = __ldg(&csrc[i]);
            float ww = __ldg(&cnrm[i]);
            float4 hv = h4f(hwv[(size_t)ss * 32 + lane]);
            a0.x = fmaf(ww, hv.x, a0.x); a0.y = fmaf(ww, hv.y, a0.y);
            a0.z = fmaf(ww, hv.z, a0.z); a0.w = fmaf(ww, hv.w, a0.w);
        }
        float4 acc;
        acc.x = (a0.x + a1.x) + (a2.x + a3.x) + b.x;
        acc.y = (a0.y + a1.y) + (a2.y + a3.y) + b.y;
        acc.z = (a0.z + a1.z) + (a2.z + a3.z) + b.z;
        acc.w = (a0.w + a1.w) + (a2.w + a3.w) + b.w;
        ((float4*)g_agg)[(size_t)node * 32 + lane] = acc;

        lsum[0] += acc.x; lsq[0] += acc.x * acc.x;
        lsum[1] += acc.y; lsq[1] += acc.y * acc.y;
        lsum[2] += acc.z; lsq[2] += acc.z * acc.z;
        lsum[3] += acc.w; lsq[3] += acc.w * acc.w;
    }

    int c = lane * 4;
#pragma unroll
    for (int j = 0; j < 4; j++) {
        atomicAdd(&s_sum[c + j], lsum[j]);
        atomicAdd(&s_sq[c + j],  lsq[j]);
    }
    __syncthreads();
    if (tid < DD) {
        atomicAdd(&colsum[tid], s_sum[tid]);
        atomicAdd(&colsq[tid],  s_sq[tid]);
    }
}

// ---------------- fused BN+residual+ReLU+LN ----------------
__global__ void __launch_bounds__(256) fuse_kernel(
    const float* __restrict__ colsum, const float* __restrict__ colsq,
    const float* __restrict__ bn_g,   const float* __restrict__ bn_b,
    const float* __restrict__ ln_g,   const float* __restrict__ ln_b,
    float* __restrict__ out, int write_out)
{
    int tid = threadIdx.x;
    int warp = tid >> 5, lane = tid & 31;
    int node = blockIdx.x * 8 + warp;
    if (node >= NN) return;

    const float inv_n = 1.f / (float)NN;
    float4 cs = ((const float4*)colsum)[lane];
    float4 cq = ((const float4*)colsq)[lane];
    float4 bg = ((const float4*)bn_g)[lane];
    float4 bb = ((const float4*)bn_b)[lane];
    float4 sc, sh;
    {
        float mu, var, rs;
        mu = cs.x * inv_n; var = cq.x * inv_n - mu * mu; rs = rsqrtf(var + EPS);
        sc.x = rs * bg.x; sh.x = bb.x - mu * sc.x;
        mu = cs.y * inv_n; var = cq.y * inv_n - mu * mu; rs = rsqrtf(var + EPS);
        sc.y = rs * bg.y; sh.y = bb.y - mu * sc.y;
        mu = cs.z * inv_n; var = cq.z * inv_n - mu * mu; rs = rsqrtf(var + EPS);
        sc.z = rs * bg.z; sh.z = bb.z - mu * sc.z;
        mu = cs.w * inv_n; var = cq.w * inv_n - mu * mu; rs = rsqrtf(var + EPS);
        sc.w = rs * bg.w; sh.w = bb.w - mu * sc.w;
    }

    float4 a = ((const float4*)g_agg)[(size_t)node * 32 + lane];
    float4 r = ((const float4*)g_hr )[(size_t)node * 32 + lane];

    float4 v;
    v.x = fmaxf(fmaf(a.x, sc.x, sh.x) + r.x, 0.f);
    v.y = fmaxf(fmaf(a.y, sc.y, sh.y) + r.y, 0.f);
    v.z = fmaxf(fmaf(a.z, sc.z, sh.z) + r.z, 0.f);
    v.w = fmaxf(fmaf(a.w, sc.w, sh.w) + r.w, 0.f);

    float sum = v.x + v.y + v.z + v.w;
    float sq  = v.x * v.x + v.y * v.y + v.z * v.z + v.w * v.w;
#pragma unroll
    for (int off = 16; off > 0; off >>= 1) {
        sum += __shfl_xor_sync(0xffffffffu, sum, off);
        sq  += __shfl_xor_sync(0xffffffffu, sq,  off);
    }
    float m   = sum * (1.f / DD);
    float var = sq * (1.f / DD) - m * m;
    float rs  = rsqrtf(var + EPS);

    float4 g = ((const float4*)ln_g)[lane];
    float4 b = ((const float4*)ln_b)[lane];
    float o[4];
    o[0] = fmaf((v.x - m) * rs, g.x, b.x);
    o[1] = fmaf((v.y - m) * rs, g.y, b.y);
    o[2] = fmaf((v.z - m) * rs, g.z, b.z);
    o[3] = fmaf((v.w - m) * rs, g.w, b.w);

    if (write_out) {
        float4 ov = make_float4(o[0], o[1], o[2], o[3]);
        ((float4*)out)[(size_t)node * 32 + lane] = ov;
    } else {
        int tile = node >> 7;
        int rr   = node & 127;
        int c    = lane * 4;
        unsigned long long hp, lp;
        split4(o, hp, lp);
        uint32_t adr = tile_off(rr, c);
        *(unsigned long long*)((char*)g_ah + (size_t)tile * TILEB + adr) = hp;
        *(unsigned long long*)((char*)g_al + (size_t)tile * TILEB + adr) = lp;
    }
}

// ---------------- launch ----------------
extern "C" void kernel_launch(void* const* d_in, const int* in_sizes, int n_in,
                              void* d_out, int out_size)
{
    const float* x      = (const float*)d_in[0];
    const void*  ei     = d_in[1];
    const float* conv_w = (const float*)d_in[2];
    const float* conv_b = (const float*)d_in[3];
    const float* bn_g   = (const float*)d_in[4];
    const float* bn_b   = (const float*)d_in[5];
    const float* res_w  = (const float*)d_in[6];
    const float* res_b  = (const float*)d_in[7];
    const float* ln_g   = (const float*)d_in[8];
    const float* ln_b   = (const float*)d_in[9];
    float*       outp   = (float*)d_out;

    __half* pHW;
    float *pHR, *pCS, *pCQ;
    cudaGetSymbolAddress((void**)&pHW, g_hw);
    cudaGetSymbolAddress((void**)&pHR, g_hr);
    cudaGetSymbolAddress((void**)&pCS, g_colsum);
    cudaGetSymbolAddress((void**)&pCQ, g_colsq);

    cudaFuncSetAttribute(gemm_conv_kernel, cudaFuncAttributeMaxDynamicSharedMemorySize, SM_TOT4);
    cudaFuncSetAttribute(gemm_res_kernel,  cudaFuncAttributeMaxDynamicSharedMemorySize, SM_TOT4);

    const int agg_grid  = (NN + 31) / 32;
    const int node_grid = (NN + 7) / 8;
    const bool have_side = (g_ss.s != nullptr);

    prep_w_kernel<<<NL * 2, 256>>>(conv_w, res_w);
    prep_x_kernel<<<(TILES * 128 * 32 + 255) / 256, 256>>>(x);
    detect_kernel<<<1, 256>>>((const int*)ei);
    gemm_conv_kernel<<<TILES, 512, SM_TOT4>>>(0, pHW);   // my #4: ncu control
    hist_kernel<<<(NE + 255) / 256, 256>>>(ei);
    offsets_kernel<<<(NN + 255) / 256, 256>>>();
    fill_kernel<<<(NE + 255) / 256, 256>>>(ei);

    for (int i = 0; i < NL; i++) {
        if (i > 0)
            gemm_conv_kernel<<<TILES, 512, SM_TOT4>>>(i, pHW);

        if (have_side) {
            // fork: res GEMM overlaps agg on side stream
            cudaEventRecord(g_ss.evA[i], 0);
            cudaStreamWaitEvent(g_ss.s, g_ss.evA[i], 0);
            gemm_res_kernel<<<TILES, 512, SM_TOT4, g_ss.s>>>(res_b + (size_t)i * DD, i, pHR);
            cudaEventRecord(g_ss.evB[i], g_ss.s);
        } else {
            gemm_res_kernel<<<TILES, 512, SM_TOT4>>>(res_b + (size_t)i * DD, i, pHR);
        }

        agg_kernel<<<agg_grid, 256>>>(conv_b + (size_t)i * DD,
                                      pCS + (size_t)i * DD, pCQ + (size_t)i * DD);

        if (have_side)
            cudaStreamWaitEvent(0, g_ss.evB[i], 0);   // join before fuse reads g_hr

        fuse_kernel<<<node_grid, 256>>>(pCS + (size_t)i * DD, pCQ + (size_t)i * DD,
                                        bn_g + (size_t)i * DD, bn_b + (size_t)i * DD,
                                        ln_g, ln_b, outp, i == NL - 1 ? 1 : 0);
    }
}

// round 17
// speedup vs baseline: 1.0676x; 1.0676x over previous
#include <cuda_runtime.h>
#include <cuda_bf16.h>
#include <cuda_fp16.h>
#include <cstdint>

#define NN 50000
#define NE 800000
#define DD 128
#define NL 4
#define EPS 1e-5f
#define TILES 391
#define TSTRB 144
#define CHB   (128 * TSTRB)
#define TILEB (2 * CHB)
#define TILE_ULL (TILEB / 8)

// ---------------- device scratch ----------------
__device__ __half g_hw[NN * DD];
__device__ float g_hr[NN * DD];
__device__ float g_agg[NN * DD];
__device__ int   g_counts[NN];
__device__ int   g_offsets[NN];
__device__ int   g_cursor[NN];
__device__ int   g_csr_src[NE];
__device__ float g_csr_norm[NE];
__device__ float g_dinv[NN];
__device__ float g_colsum[NL * DD];
__device__ float g_colsq[NL * DD];
__device__ int   g_total;
__device__ int   g_is64;
__device__ unsigned long long g_ah[TILES * TILE_ULL];
__device__ unsigned long long g_al[TILES * TILE_ULL];
__device__ unsigned long long g_wt[NL * 2 * 2 * TILE_ULL];

// ---------------- helpers ----------------
__device__ __forceinline__ uint32_t smem_u32(const void* p) {
    uint32_t a;
    asm("{ .reg .u64 t; cvta.to.shared.u64 t, %1; cvt.u32.u64 %0, t; }" : "=r"(a) : "l"(p));
    return a;
}
__device__ __forceinline__ void cp16(uint32_t dst, const void* src) {
    asm volatile("cp.async.cg.shared.global [%0], [%1], 16;" :: "r"(dst), "l"(src));
}
__device__ __forceinline__ void cp_commit_wait() {
    asm volatile("cp.async.commit_group;");
    asm volatile("cp.async.wait_group 0;" ::: "memory");
}
__device__ __forceinline__ void ldm_x4(uint32_t a, uint32_t* r) {
    asm volatile("ldmatrix.sync.aligned.m8n8.x4.shared.b16 {%0,%1,%2,%3}, [%4];"
                 : "=r"(r[0]), "=r"(r[1]), "=r"(r[2]), "=r"(r[3]) : "r"(a));
}
__device__ __forceinline__ void mma16816(float* d, const uint32_t* a, const uint32_t* b) {
    asm volatile(
        "mma.sync.aligned.m16n8k16.row.col.f32.bf16.bf16.f32 "
        "{%0,%1,%2,%3}, {%4,%5,%6,%7}, {%8,%9}, {%0,%1,%2,%3};"
        : "+f"(d[0]), "+f"(d[1]), "+f"(d[2]), "+f"(d[3])
        : "r"(a[0]), "r"(a[1]), "r"(a[2]), "r"(a[3]), "r"(b[0]), "r"(b[1]));
}
__device__ __forceinline__ void split4(const float* v, unsigned long long& hp, unsigned long long& lp) {
    unsigned int hu[2], lu[2];
#pragma unroll
    for (int j = 0; j < 2; j++) {
        __nv_bfloat16 h0 = __float2bfloat16(v[2 * j + 0]);
        __nv_bfloat16 h1 = __float2bfloat16(v[2 * j + 1]);
        __nv_bfloat16 l0 = __float2bfloat16(v[2 * j + 0] - __bfloat162float(h0));
        __nv_bfloat16 l1 = __float2bfloat16(v[2 * j + 1] - __bfloat162float(h1));
        unsigned short a = *(unsigned short*)&h0, b = *(unsigned short*)&h1;
        unsigned short c = *(unsigned short*)&l0, d = *(unsigned short*)&l1;
        hu[j] = (unsigned)a | ((unsigned)b << 16);
        lu[j] = (unsigned)c | ((unsigned)d << 16);
    }
    hp = (unsigned long long)hu[0] | ((unsigned long long)hu[1] << 32);
    lp = (unsigned long long)lu[0] | ((unsigned long long)lu[1] << 32);
}
__device__ __forceinline__ uint32_t tile_off(int r, int k) {
    return (uint32_t)((k >> 6) * CHB + r * TSTRB + (k & 63) * 2);
}
__device__ __forceinline__ float4 h4f(uint2 u) {
    __half2 p0 = *(__half2*)&u.x;
    __half2 p1 = *(__half2*)&u.y;
    float2 f0 = __half22float2(p0);
    float2 f1 = __half22float2(p1);
    return make_float4(f0.x, f0.y, f1.x, f1.y);
}

// ---------------- detect dtype + zero counts/stats ----------------
__global__ void detect_kernel(const int* __restrict__ ei32) {
    __shared__ int s_or;
    if (threadIdx.x == 0) { s_or = 0; g_total = 0; }
    __syncthreads();
    int acc = 0;
    for (int i = threadIdx.x; i < 2048; i += blockDim.x)
        acc |= ei32[2 * i + 1];
    atomicOr(&s_or, acc);
    for (int i = threadIdx.x; i < NL * DD; i += blockDim.x) {
        g_colsum[i] = 0.f;
        g_colsq[i]  = 0.f;
    }
    for (int i = threadIdx.x; i < NN; i += blockDim.x) g_counts[i] = 0;
    __syncthreads();
    if (threadIdx.x == 0) g_is64 = (s_or == 0) ? 1 : 0;
}
__device__ __forceinline__ int edge_at(const void* ei, long long idx) {
    if (g_is64) return (int)((const long long*)ei)[idx];
    return ((const int*)ei)[idx];
}
__global__ void hist_kernel(const void* __restrict__ ei) {
    int e = blockIdx.x * blockDim.x + threadIdx.x;
    if (e < NE) {
        int dst = edge_at(ei, (long long)NE + e);
        if ((unsigned)dst < NN) atomicAdd(&g_counts[dst], 1);
    }
}
__global__ void offsets_kernel() {
    int i    = blockIdx.x * blockDim.x + threadIdx.x;
    int lane = threadIdx.x & 31;
    int v = (i < NN) ? g_counts[i] : 0;
    int s = v;
#pragma unroll
    for (int off = 1; off < 32; off <<= 1) {
        int t = __shfl_up_sync(0xffffffffu, s, off);
        if (lane >= off) s += t;
    }
    int wtot = __shfl_sync(0xffffffffu, s, 31);
    int base = 0;
    if (lane == 0) base = atomicAdd(&g_total, wtot);
    base = __shfl_sync(0xffffffffu, base, 0);
    if (i < NN) {
        g_offsets[i] = base + s - v;
        g_cursor[i]  = base + s - v;
        g_dinv[i]    = rsqrtf((float)(v + 2));
    }
}
__global__ void fill_kernel(const void* __restrict__ ei) {
    int e = blockIdx.x * blockDim.x + threadIdx.x;
    if (e < NE) {
        int src = edge_at(ei, e);
        int dst = edge_at(ei, (long long)NE + e);
        if ((unsigned)src < NN && (unsigned)dst < NN) {
            int p = atomicAdd(&g_cursor[dst], 1);
            g_csr_src[p] = src;
            g_csr_norm[p] = g_dinv[src] * g_dinv[dst];
        }
    }
}

// ---------------- weight prep ----------------
__global__ void prep_w_kernel(const float* __restrict__ conv_w, const float* __restrict__ res_w) {
    int l = blockIdx.x >> 1, mat = blockIdx.x & 1;
    const float* W = (mat ? res_w : conv_w) + (size_t)l * DD * DD;
    char* hi = (char*)(g_wt + ((size_t)(l * 2 + mat) * 2 + 0) * TILE_ULL);
    char* lo = (char*)(g_wt + ((size_t)(l * 2 + mat) * 2 + 1) * TILE_ULL);
    for (int idx = threadIdx.x; idx < 128 * 32; idx += blockDim.x) {
        int r = idx & 127;
        int c = (idx >> 7) * 4;
        float v[4];
#pragma unroll
        for (int j = 0; j < 4; j++) v[j] = W[(size_t)(c + j) * DD + r];
        unsigned long long hp, lp;
        split4(v, hp, lp);
        uint32_t a = tile_off(r, c);
        *(unsigned long long*)(hi + a) = hp;
        *(unsigned long long*)(lo + a) = lp;
    }
}

// ---------------- x prep ----------------
__global__ void prep_x_kernel(const float* __restrict__ x) {
    int idx = blockIdx.x * blockDim.x + threadIdx.x;
    if (idx >= TILES * 128 * 32) return;
    int tile = idx >> 12;
    int rem  = idx & 4095;
    int r = rem >> 5;
    int c = (rem & 31) * 4;
    int row = tile * 128 + r;
    float v[4] = {0.f, 0.f, 0.f, 0.f};
    if (row < NN) {
        float4 t = *((const float4*)(x + (size_t)row * DD + c));
        v[0] = t.x; v[1] = t.y; v[2] = t.z; v[3] = t.w;
    }
    unsigned long long hp, lp;
    split4(v, hp, lp);
    uint32_t a = tile_off(r, c);
    *(unsigned long long*)((char*)g_ah + (size_t)tile * TILEB + a) = hp;
    *(unsigned long long*)((char*)g_al + (size_t)tile * TILEB + a) = lp;
}

// ---------------- fully-resident dual tensor-core GEMM (R15 form) ----------
#define SM_AH 0
#define SM_AL TILEB
#define SM_W  (2 * TILEB)
#define SM_TOT (6 * TILEB)        // 221184

__global__ void __launch_bounds__(512, 1) gemm_mma_kernel(
    const float* __restrict__ res_b, int layer,
    __half* __restrict__ C1, float* __restrict__ C2)
{
    extern __shared__ char smem[];
    uint32_t sb = smem_u32(smem);
    int tid = threadIdx.x, lane = tid & 31, w = tid >> 5;
    int wm = w >> 2, wn = w & 3;
    int tile = blockIdx.x;

    const char* gAh = (const char*)g_ah + (size_t)tile * TILEB;
    const char* gAl = (const char*)g_al + (size_t)tile * TILEB;
    const char* gW  = (const char*)(g_wt + (size_t)layer * 2 * 2 * TILE_ULL);

    for (int i = tid; i < TILEB / 16; i += 512) {
        cp16(sb + SM_AH + i * 16, gAh + i * 16);
        cp16(sb + SM_AL + i * 16, gAl + i * 16);
#pragma unroll
        for (int mt = 0; mt < 4; mt++)
            cp16(sb + SM_W + mt * TILEB + i * 16, gW + (size_t)mt * TILEB + i * 16);
    }

    float acc[2][2][4][4];
#pragma unroll
    for (int a = 0; a < 2; a++)
#pragma unroll
        for (int b = 0; b < 2; b++)
#pragma unroll
            for (int c = 0; c < 4; c++)
#pragma unroll
                for (int d = 0; d < 4; d++) acc[a][b][c][d] = 0.f;

    int la  = (lane & 7) + ((lane & 8) ? 8 : 0);
    uint32_t aka = (lane & 16) ? 16 : 0;
    int lb  = (lane & 7) + ((lane & 16) ? 8 : 0);
    uint32_t akb = (lane & 8) ? 16 : 0;

    uint32_t aA = sb + SM_AH + (uint32_t)(wm * 32 + la) * TSTRB + aka;
    uint32_t aB = sb + SM_W + (uint32_t)(wn * 32 + lb) * TSTRB + akb;

    cp_commit_wait();
    __syncthreads();

#pragma unroll
    for (int ks = 0; ks < 8; ks++) {
        uint32_t kb = (uint32_t)((ks >> 2) * CHB + (ks & 3) * 32);
        uint32_t ah0[4], ah1[4], al0[4], al1[4];
        ldm_x4(aA + kb, ah0);
        ldm_x4(aA + 16 * TSTRB + kb, ah1);
        ldm_x4(aA + TILEB + kb, al0);
        ldm_x4(aA + TILEB + 16 * TSTRB + kb, al1);
#pragma unroll
        for (int mat = 0; mat < 2; mat++) {
            uint32_t bh[4][2];
#pragma unroll
            for (int g2 = 0; g2 < 2; g2++) {
                uint32_t t[4];
                ldm_x4(aB + (uint32_t)(mat * 2) * TILEB + (uint32_t)g2 * 16 * TSTRB + kb, t);
                bh[2 * g2][0] = t[0]; bh[2 * g2][1] = t[1];
                bh[2 * g2 + 1][0] = t[2]; bh[2 * g2 + 1][1] = t[3];
            }
#pragma unroll
            for (int n = 0; n < 4; n++) {
                mma16816(acc[mat][0][n], ah0, bh[n]);
                mma16816(acc[mat][1][n], ah1, bh[n]);
                mma16816(acc[mat][0][n], al0, bh[n]);
                mma16816(acc[mat][1][n], al1, bh[n]);
            }
            uint32_t bl[4][2];
#pragma unroll
            for (int g2 = 0; g2 < 2; g2++) {
                uint32_t t[4];
                ldm_x4(aB + (uint32_t)(mat * 2 + 1) * TILEB + (uint32_t)g2 * 16 * TSTRB + kb, t);
                bl[2 * g2][0] = t[0]; bl[2 * g2][1] = t[1];
                bl[2 * g2 + 1][0] = t[2]; bl[2 * g2 + 1][1] = t[3];
            }
#pragma unroll
            for (int n = 0; n < 4; n++) {
                mma16816(acc[mat][0][n], ah0, bl[n]);
                mma16816(acc[mat][1][n], ah1, bl[n]);
            }
        }
    }

    int grp = lane >> 2, tig = lane & 3;
#pragma unroll
    for (int ni = 0; ni < 4; ni++) {
        int col = wn * 32 + ni * 8 + tig * 2;
#pragma unroll
        for (int mi = 0; mi < 2; mi++) {
            int row0 = tile * 128 + wm * 32 + mi * 16 + grp;
            if (row0 < NN) {
                __half2 o = __floats2half2_rn(acc[0][mi][ni][0], acc[0][mi][ni][1]);
                *(__half2*)(C1 + (size_t)row0 * DD + col) = o;
            }
            if (row0 + 8 < NN) {
                __half2 o = __floats2half2_rn(acc[0][mi][ni][2], acc[0][mi][ni][3]);
                *(__half2*)(C1 + (size_t)(row0 + 8) * DD + col) = o;
            }
        }
    }
#pragma unroll
    for (int ni = 0; ni < 4; ni++) {
        int col = wn * 32 + ni * 8 + tig * 2;
        float2 bv = *(const float2*)&res_b[col];
#pragma unroll
        for (int mi = 0; mi < 2; mi++) {
            int row0 = tile * 128 + wm * 32 + mi * 16 + grp;
            if (row0 < NN) {
                float2 o = make_float2(acc[1][mi][ni][0] + bv.x, acc[1][mi][ni][1] + bv.y);
                *(float2*)(C2 + (size_t)row0 * DD + col) = o;
            }
            if (row0 + 8 < NN) {
                float2 o = make_float2(acc[1][mi][ni][2] + bv.x, acc[1][mi][ni][3] + bv.y);
                *(float2*)(C2 + (size_t)(row0 + 8) * DD + col) = o;
            }
        }
    }
}

// ---------------- aggregation + BN stats: 4 nodes/warp, fp16 gathers, prefetched meta ----
__global__ void __launch_bounds__(256) agg_kernel(const float* __restrict__ conv_b,
                                                  float* __restrict__ colsum,
                                                  float* __restrict__ colsq)
{
    __shared__ float s_sum[DD];
    __shared__ float s_sq[DD];
    int tid = threadIdx.x;
    if (tid < DD) { s_sum[tid] = 0.f; s_sq[tid] = 0.f; }
    __syncthreads();

    int warp = tid >> 5, lane = tid & 31;
    int node0 = blockIdx.x * 32 + warp * 4;
    const uint2* __restrict__ hwv = (const uint2*)g_hw;
    const int*   __restrict__ csrc = g_csr_src;
    const float* __restrict__ cnrm = g_csr_norm;
    float4 b = ((const float4*)conv_b)[lane];

    // prefetch per-node metadata for all 4 nodes up front (independent loads)
    int   soff[4], cnt[4];
    float dinv[4];
#pragma unroll
    for (int nn = 0; nn < 4; nn++) {
        int node = node0 + nn;
        if (node < NN) {
            soff[nn] = __ldg(&g_offsets[node]);
            cnt[nn]  = __ldg(&g_counts[node]);
            dinv[nn] = __ldg(&g_dinv[node]);
        } else {
            soff[nn] = 0; cnt[nn] = 0; dinv[nn] = 0.f;
        }
    }

    float lsum[4] = {0.f, 0.f, 0.f, 0.f};
    float lsq[4]  = {0.f, 0.f, 0.f, 0.f};

#pragma unroll
    for (int nn = 0; nn < 4; nn++) {
        int node = node0 + nn;
        if (node >= NN) break;

        float di = dinv[nn];
        float ws = 2.f * di * di;
        float4 hs = h4f(hwv[(size_t)node * 32 + lane]);
        float4 a0, a1, a2, a3;
        a0.x = ws * hs.x; a0.y = ws * hs.y; a0.z = ws * hs.z; a0.w = ws * hs.w;
        a1 = make_float4(0.f, 0.f, 0.f, 0.f);
        a2 = make_float4(0.f, 0.f, 0.f, 0.f);
        a3 = make_float4(0.f, 0.f, 0.f, 0.f);

        int s = soff[nn];
        int e = s + cnt[nn];
        int i = s;
        for (; i + 4 <= e; i += 4) {
            int   s0 = __ldg(&csrc[i + 0]), s1 = __ldg(&csrc[i + 1]);
            int   s2 = __ldg(&csrc[i + 2]), s3 = __ldg(&csrc[i + 3]);
            float w0 = __ldg(&cnrm[i + 0]), w1 = __ldg(&cnrm[i + 1]);
            float w2 = __ldg(&cnrm[i + 2]), w3 = __ldg(&cnrm[i + 3]);
            float4 h0 = h4f(hwv[(size_t)s0 * 32 + lane]);
            float4 h1 = h4f(hwv[(size_t)s1 * 32 + lane]);
            float4 h2 = h4f(hwv[(size_t)s2 * 32 + lane]);
            float4 h3 = h4f(hwv[(size_t)s3 * 32 + lane]);
            a0.x = fmaf(w0, h0.x, a0.x); a0.y = fmaf(w0, h0.y, a0.y);
            a0.z = fmaf(w0, h0.z, a0.z); a0.w = fmaf(w0, h0.w, a0.w);
            a1.x = fmaf(w1, h1.x, a1.x); a1.y = fmaf(w1, h1.y, a1.y);
            a1.z = fmaf(w1, h1.z, a1.z); a1.w = fmaf(w1, h1.w, a1.w);
            a2.x = fmaf(w2, h2.x, a2.x); a2.y = fmaf(w2, h2.y, a2.y);
            a2.z = fmaf(w2, h2.z, a2.z); a2.w = fmaf(w2, h2.w, a2.w);
            a3.x = fmaf(w3, h3.x, a3.x); a3.y = fmaf(w3, h3.y, a3.y);
            a3.z = fmaf(w3, h3.z, a3.z); a3.w = fmaf(w3, h3.w, a3.w);
        }
        for (; i < e; i++) {
            int   ss = __ldg(&csrc[i]);
            float ww = __ldg(&cnrm[i]);
            float4 hv = h4f(hwv[(size_t)ss * 32 + lane]);
            a0.x = fmaf(ww, hv.x, a0.x); a0.y = fmaf(ww, hv.y, a0.y);
            a0.z = fmaf(ww, hv.z, a0.z); a0.w = fmaf(ww, hv.w, a0.w);
        }
        float4 acc;
        acc.x = (a0.x + a1.x) + (a2.x + a3.x) + b.x;
        acc.y = (a0.y + a1.y) + (a2.y + a3.y) + b.y;
        acc.z = (a0.z + a1.z) + (a2.z + a3.z) + b.z;
        acc.w = (a0.w + a1.w) + (a2.w + a3.w) + b.w;
        ((float4*)g_agg)[(size_t)node * 32 + lane] = acc;

        lsum[0] += acc.x; lsq[0] += acc.x * acc.x;
        lsum[1] += acc.y; lsq[1] += acc.y * acc.y;
        lsum[2] += acc.z; lsq[2] += acc.z * acc.z;
        lsum[3] += acc.w; lsq[3] += acc.w * acc.w;
    }

    int c = lane * 4;
#pragma unroll
    for (int j = 0; j < 4; j++) {
        atomicAdd(&s_sum[c + j], lsum[j]);
        atomicAdd(&s_sq[c + j],  lsq[j]);
    }
    __syncthreads();
    if (tid < DD) {
        atomicAdd(&colsum[tid], s_sum[tid]);
        atomicAdd(&colsq[tid],  s_sq[tid]);
    }
}

// ---------------- fused BN+residual+ReLU+LN ----------------
__global__ void __launch_bounds__(256) fuse_kernel(
    const float* __restrict__ colsum, const float* __restrict__ colsq,
    const float* __restrict__ bn_g,   const float* __restrict__ bn_b,
    const float* __restrict__ ln_g,   const float* __restrict__ ln_b,
    float* __restrict__ out, int write_out)
{
    int tid = threadIdx.x;
    int warp = tid >> 5, lane = tid & 31;
    int node = blockIdx.x * 8 + warp;
    if (node >= NN) return;

    const float inv_n = 1.f / (float)NN;
    float4 cs = ((const float4*)colsum)[lane];
    float4 cq = ((const float4*)colsq)[lane];
    float4 bg = ((const float4*)bn_g)[lane];
    float4 bb = ((const float4*)bn_b)[lane];
    float4 sc, sh;
    {
        float mu, var, rs;
        mu = cs.x * inv_n; var = cq.x * inv_n - mu * mu; rs = rsqrtf(var + EPS);
        sc.x = rs * bg.x; sh.x = bb.x - mu * sc.x;
        mu = cs.y * inv_n; var = cq.y * inv_n - mu * mu; rs = rsqrtf(var + EPS);
        sc.y = rs * bg.y; sh.y = bb.y - mu * sc.y;
        mu = cs.z * inv_n; var = cq.z * inv_n - mu * mu; rs = rsqrtf(var + EPS);
        sc.z = rs * bg.z; sh.z = bb.z - mu * sc.z;
        mu = cs.w * inv_n; var = cq.w * inv_n - mu * mu; rs = rsqrtf(var + EPS);
        sc.w = rs * bg.w; sh.w = bb.w - mu * sc.w;
    }

    float4 a = ((const float4*)g_agg)[(size_t)node * 32 + lane];
    float4 r = ((const float4*)g_hr )[(size_t)node * 32 + lane];

    float4 v;
    v.x = fmaxf(fmaf(a.x, sc.x, sh.x) + r.x, 0.f);
    v.y = fmaxf(fmaf(a.y, sc.y, sh.y) + r.y, 0.f);
    v.z = fmaxf(fmaf(a.z, sc.z, sh.z) + r.z, 0.f);
    v.w = fmaxf(fmaf(a.w, sc.w, sh.w) + r.w, 0.f);

    float sum = v.x + v.y + v.z + v.w;
    float sq  = v.x * v.x + v.y * v.y + v.z * v.z + v.w * v.w;
#pragma unroll
    for (int off = 16; off > 0; off >>= 1) {
        sum += __shfl_xor_sync(0xffffffffu, sum, off);
        sq  += __shfl_xor_sync(0xffffffffu, sq,  off);
    }
    float m   = sum * (1.f / DD);
    float var = sq * (1.f / DD) - m * m;
    float rs  = rsqrtf(var + EPS);

    float4 g = ((const float4*)ln_g)[lane];
    float4 b = ((const float4*)ln_b)[lane];
    float o[4];
    o[0] = fmaf((v.x - m) * rs, g.x, b.x);
    o[1] = fmaf((v.y - m) * rs, g.y, b.y);
    o[2] = fmaf((v.z - m) * rs, g.z, b.z);
    o[3] = fmaf((v.w - m) * rs, g.w, b.w);

    if (write_out) {
        float4 ov = make_float4(o[0], o[1], o[2], o[3]);
        ((float4*)out)[(size_t)node * 32 + lane] = ov;
    } else {
        int tile = node >> 7;
        int rr   = node & 127;
        int c    = lane * 4;
        unsigned long long hp, lp;
        split4(o, hp, lp);
        uint32_t adr = tile_off(rr, c);
        *(unsigned long long*)((char*)g_ah + (size_t)tile * TILEB + adr) = hp;
        *(unsigned long long*)((char*)g_al + (size_t)tile * TILEB + adr) = lp;
    }
}

// ---------------- launch ----------------
extern "C" void kernel_launch(void* const* d_in, const int* in_sizes, int n_in,
                              void* d_out, int out_size)
{
    const float* x      = (const float*)d_in[0];
    const void*  ei     = d_in[1];
    const float* conv_w = (const float*)d_in[2];
    const float* conv_b = (const float*)d_in[3];
    const float* bn_g   = (const float*)d_in[4];
    const float* bn_b   = (const float*)d_in[5];
    const float* res_w  = (const float*)d_in[6];
    const float* res_b  = (const float*)d_in[7];
    const float* ln_g   = (const float*)d_in[8];
    const float* ln_b   = (const float*)d_in[9];
    float*       outp   = (float*)d_out;

    __half* pHW;
    float *pHR, *pCS, *pCQ;
    cudaGetSymbolAddress((void**)&pHW, g_hw);
    cudaGetSymbolAddress((void**)&pHR, g_hr);
    cudaGetSymbolAddress((void**)&pCS, g_colsum);
    cudaGetSymbolAddress((void**)&pCQ, g_colsq);

    cudaFuncSetAttribute(gemm_mma_kernel, cudaFuncAttributeMaxDynamicSharedMemorySize, SM_TOT);

    const int agg_grid  = (NN + 31) / 32;
    const int node_grid = (NN + 7) / 8;

    prep_w_kernel<<<NL * 2, 256>>>(conv_w, res_w);
    prep_x_kernel<<<(TILES * 128 * 32 + 255) / 256, 256>>>(x);
    detect_kernel<<<1, 256>>>((const int*)ei);
    gemm_mma_kernel<<<TILES, 512, SM_TOT>>>(res_b, 0, pHW, pHR);
    hist_kernel<<<(NE + 255) / 256, 256>>>(ei);
    offsets_kernel<<<(NN + 255) / 256, 256>>>();
    fill_kernel<<<(NE + 255) / 256, 256>>>(ei);

    for (int i = 0; i < NL; i++) {
        if (i > 0)
            gemm_mma_kernel<<<TILES, 512, SM_TOT>>>(res_b + (size_t)i * DD, i, pHW, pHR);
        agg_kernel<<<agg_grid, 256>>>(conv_b + (size_t)i * DD,
                                      pCS + (size_t)i * DD, pCQ + (size_t)i * DD);
        fuse_kernel<<<node_grid, 256>>>(pCS + (size_t)i * DD, pCQ + (size_t)i * DD,
                                        bn_g + (size_t)i * DD, bn_b + (size_t)i * DD,
                                        ln_g, ln_b, outp, i == NL - 1 ? 1 : 0);
    }
}